// round 1
// baseline (speedup 1.0000x reference)
#include <cuda_runtime.h>
#include <math.h>

#define Bn 4
#define Tn 8
#define Hn 256
#define Wn 256
#define Nn (Bn*Tn*Hn*Wn)   // 2,097,152

// Scratch (static device globals: allocation-free per harness rules)
__device__ float  g_params[7 * Nn];   // 0:kap2 1:m1 2:m2 3:hxx 4:hyy 5:hxys 6:D
__device__ float  g_y[Nn];
__device__ double g_logD;
__device__ double g_xQx;

__global__ void init_kernel() { g_logD = 0.0; g_xQx = 0.0; }

__device__ __forceinline__ float block_reduce_sum(float v) {
    __shared__ float red[8];
    #pragma unroll
    for (int o = 16; o > 0; o >>= 1) v += __shfl_down_sync(0xffffffffu, v, o);
    int lane = threadIdx.x & 31, wid = threadIdx.x >> 5;
    if (lane == 0) red[wid] = v;
    __syncthreads();
    if (wid == 0) {
        v = (lane < 8) ? red[lane] : 0.f;
        #pragma unroll
        for (int o = 4; o > 0; o >>= 1) v += __shfl_down_sync(0xffffffffu, v, o);
    }
    return v;  // valid on thread 0
}

// ---------------------------------------------------------------------------
// Conv 3x3 (8 -> 64 ch) + nonlinearities + param store + sum(log D)
// Block: 256 threads, 32x32 output tile. grid (8, 8, B)
// ---------------------------------------------------------------------------
__global__ __launch_bounds__(256, 2)
void conv_kernel(const float* __restrict__ x, const float* __restrict__ w) {
    __shared__ float xs[8][34][34];
    __shared__ __align__(16) float ws[72][8];   // [k = ic*9+kh*3+kw][g]

    const int tid = threadIdx.x;
    const int tx  = tid & 31;
    const int ty  = tid >> 5;
    const int b   = blockIdx.z;
    const int h0  = blockIdx.y * 32;
    const int w0  = blockIdx.x * 32;

    // Load x patch with halo (zero padded)
    const float* xb = x + b * Tn * Hn * Wn;
    for (int i = tid; i < 8 * 34 * 34; i += 256) {
        int ic  = i / 1156;
        int rem = i - ic * 1156;
        int ly  = rem / 34;
        int lx  = rem - ly * 34;
        int gh  = h0 - 1 + ly;
        int gw  = w0 - 1 + lx;
        float v = 0.f;
        if ((unsigned)gh < (unsigned)Hn && (unsigned)gw < (unsigned)Wn)
            v = xb[(ic * Hn + gh) * Wn + gw];
        xs[ic][ly][lx] = v;
    }

    float local_logD = 0.f;

    for (int t = 0; t < Tn; ++t) {
        __syncthreads();   // ws reuse guard + xs ready on first iter
        // Stage weights for the 8 oc's {g*8 + t}
        for (int j = tid; j < 576; j += 256) {
            int k = j >> 3;
            int g = j & 7;
            ws[k][g] = w[(g * 8 + t) * 72 + k];
        }
        __syncthreads();

        float acc[4][8];
        #pragma unroll
        for (int r = 0; r < 4; ++r)
            #pragma unroll
            for (int g = 0; g < 8; ++g) acc[r][g] = 0.f;

        for (int ic = 0; ic < 8; ++ic) {
            #pragma unroll
            for (int kh = 0; kh < 3; ++kh) {
                #pragma unroll
                for (int kw = 0; kw < 3; ++kw) {
                    const int k = ic * 9 + kh * 3 + kw;
                    float4 wa = *(const float4*)&ws[k][0];
                    float4 wb = *(const float4*)&ws[k][4];
                    float xv[4];
                    #pragma unroll
                    for (int r = 0; r < 4; ++r)
                        xv[r] = xs[ic][ty * 4 + r + kh][tx + kw];
                    #pragma unroll
                    for (int r = 0; r < 4; ++r) {
                        acc[r][0] += xv[r] * wa.x;
                        acc[r][1] += xv[r] * wa.y;
                        acc[r][2] += xv[r] * wa.z;
                        acc[r][3] += xv[r] * wa.w;
                        acc[r][4] += xv[r] * wb.x;
                        acc[r][5] += xv[r] * wb.y;
                        acc[r][6] += xv[r] * wb.z;
                        acc[r][7] += xv[r] * wb.w;
                    }
                }
            }
        }

        // Epilogue: nonlinearities + store 7 coefficient fields
        const int wglob = w0 + tx;
        #pragma unroll
        for (int r = 0; r < 4; ++r) {
            int hglob = h0 + ty * 4 + r;
            int idx = ((b * Tn + t) * Hn + hglob) * Wn + wglob;

            float sg0 = 1.f / (1.f + __expf(-acc[r][0]));
            float kap = 0.99f * sg0 + 0.01f;
            float kap2 = kap * kap;
            float hxx = 0.99f * (1.f / (1.f + __expf(-acc[r][3]))) + 0.01f;
            float hyy = 0.99f * (1.f / (1.f + __expf(-acc[r][6]))) + 0.01f;
            float hxys = 0.1f * (tanhf(acc[r][4]) + tanhf(acc[r][5]));
            float tau = 9.9f * (1.f / (1.f + __expf(-acc[r][7]))) + 0.1f;
            float Dv = 1.f / (tau * tau);
            local_logD += -2.f * __logf(tau);

            g_params[0 * Nn + idx] = kap2;
            g_params[1 * Nn + idx] = acc[r][1];
            g_params[2 * Nn + idx] = acc[r][2];
            g_params[3 * Nn + idx] = hxx;
            g_params[4 * Nn + idx] = hyy;
            g_params[5 * Nn + idx] = hxys;
            g_params[6 * Nn + idx] = Dv;
        }
    }

    __syncthreads();
    float s = block_reduce_sum(local_logD);
    if (threadIdx.x == 0) atomicAdd(&g_logD, (double)s);
}

// ---------------------------------------------------------------------------
// A(u): variable-coefficient 3x3 stencil with zero (Dirichlet) extension.
// A(u) = kap2*u + 0.5*m1*(E-W) + 0.5*m2*(S-N)
//        - hxx*(E+W-2C) - hyy*(S+N-2C) - 0.25*hxys*(SE-NE-SW+NW)
// ---------------------------------------------------------------------------
__global__ __launch_bounds__(256)
void applyA_kernel(const float* __restrict__ x) {
    __shared__ float us[34][34];
    const int tid = threadIdx.x;
    const int tx  = tid & 31;
    const int ty  = tid >> 5;
    const int bt  = blockIdx.z;       // b*T + t
    const int h0  = blockIdx.y * 32;
    const int w0  = blockIdx.x * 32;

    const float* up = x + bt * Hn * Wn;
    for (int i = tid; i < 34 * 34; i += 256) {
        int ly = i / 34, lx = i - ly * 34;
        int gh = h0 - 1 + ly, gw = w0 - 1 + lx;
        us[ly][lx] = ((unsigned)gh < (unsigned)Hn && (unsigned)gw < (unsigned)Wn)
                         ? up[gh * Wn + gw] : 0.f;
    }
    __syncthreads();

    #pragma unroll
    for (int r = 0; r < 4; ++r) {
        int hl = ty * 4 + r;
        int idx = (bt * Hn + h0 + hl) * Wn + w0 + tx;
        float c  = us[hl + 1][tx + 1];
        float e  = us[hl + 1][tx + 2];
        float wv = us[hl + 1][tx + 0];
        float s  = us[hl + 2][tx + 1];
        float n  = us[hl + 0][tx + 1];
        float se = us[hl + 2][tx + 2];
        float ne = us[hl + 0][tx + 2];
        float sw = us[hl + 2][tx + 0];
        float nw = us[hl + 0][tx + 0];

        float kap2 = g_params[0 * Nn + idx];
        float m1   = g_params[1 * Nn + idx];
        float m2   = g_params[2 * Nn + idx];
        float hxx  = g_params[3 * Nn + idx];
        float hyy  = g_params[4 * Nn + idx];
        float hxys = g_params[5 * Nn + idx];

        float Au = kap2 * c
                 + 0.5f * m1 * (e - wv)
                 + 0.5f * m2 * (s - n)
                 - hxx * (e + wv - 2.f * c)
                 - hyy * (s + n - 2.f * c)
                 - 0.25f * hxys * (se - ne - sw + nw);
        g_y[idx] = Au;
    }
}

// ---------------------------------------------------------------------------
// z = A(y); r = x + z - x_prev; accumulate sum(D * r^2)
// ---------------------------------------------------------------------------
__global__ __launch_bounds__(256)
void applyA2_kernel(const float* __restrict__ x) {
    __shared__ float us[34][34];
    const int tid = threadIdx.x;
    const int tx  = tid & 31;
    const int ty  = tid >> 5;
    const int bt  = blockIdx.z;
    const int t   = bt & (Tn - 1);
    const int h0  = blockIdx.y * 32;
    const int w0  = blockIdx.x * 32;

    const float* up = g_y + bt * Hn * Wn;
    for (int i = tid; i < 34 * 34; i += 256) {
        int ly = i / 34, lx = i - ly * 34;
        int gh = h0 - 1 + ly, gw = w0 - 1 + lx;
        us[ly][lx] = ((unsigned)gh < (unsigned)Hn && (unsigned)gw < (unsigned)Wn)
                         ? up[gh * Wn + gw] : 0.f;
    }
    __syncthreads();

    float local = 0.f;
    #pragma unroll
    for (int r = 0; r < 4; ++r) {
        int hl = ty * 4 + r;
        int idx = (bt * Hn + h0 + hl) * Wn + w0 + tx;
        float c  = us[hl + 1][tx + 1];
        float e  = us[hl + 1][tx + 2];
        float wv = us[hl + 1][tx + 0];
        float s  = us[hl + 2][tx + 1];
        float n  = us[hl + 0][tx + 1];
        float se = us[hl + 2][tx + 2];
        float ne = us[hl + 0][tx + 2];
        float sw = us[hl + 2][tx + 0];
        float nw = us[hl + 0][tx + 0];

        float kap2 = g_params[0 * Nn + idx];
        float m1   = g_params[1 * Nn + idx];
        float m2   = g_params[2 * Nn + idx];
        float hxx  = g_params[3 * Nn + idx];
        float hyy  = g_params[4 * Nn + idx];
        float hxys = g_params[5 * Nn + idx];
        float Dv   = g_params[6 * Nn + idx];

        float z = kap2 * c
                + 0.5f * m1 * (e - wv)
                + 0.5f * m2 * (s - n)
                - hxx * (e + wv - 2.f * c)
                - hyy * (s + n - 2.f * c)
                - 0.25f * hxys * (se - ne - sw + nw);

        float xc    = x[idx];
        float xprev = (t > 0) ? x[idx - Hn * Wn] : 0.f;
        float rr = xc + z - xprev;   // Mx - x_prev, dt = 1
        local += Dv * rr * rr;
    }

    __syncthreads();
    float ssum = block_reduce_sum(local);
    if (threadIdx.x == 0) atomicAdd(&g_xQx, (double)ssum);
}

__global__ void final_kernel(float* out) {
    out[0] = (float)(0.5 * (g_xQx - g_logD));
}

extern "C" void kernel_launch(void* const* d_in, const int* in_sizes, int n_in,
                              void* d_out, int out_size) {
    const float* x = (const float*)d_in[0];
    const float* w = (const float*)d_in[1];
    float* out = (float*)d_out;

    init_kernel<<<1, 1>>>();
    conv_kernel<<<dim3(8, 8, Bn), 256>>>(x, w);
    applyA_kernel<<<dim3(8, 8, Bn * Tn), 256>>>(x);
    applyA2_kernel<<<dim3(8, 8, Bn * Tn), 256>>>(x);
    final_kernel<<<1, 1>>>(out);
}